// round 11
// baseline (speedup 1.0000x reference)
#include <cuda_runtime.h>
#include <cuda_bf16.h>
#include <cstdint>

#define BB 4
#define TT 4096
#define DD 1024
#define HH 64
#define NT (BB*TT)
#define NQB (TT/128)

#define NEGINF __int_as_float(0xff800000)
#define MFLOOR (-1e30f)

// attn smem geometry (uint16 units): row pad 72 (144 B, 16B-aligned rows for cp.async)
#define APAD 72
#define QSZ  (128*APAD)          // 9216
#define TSZ  (64*APAD)           // 4608 per array
#define BUF0 (2*QSZ)             // 18432
#define BUFSZ (4*TSZ)            // 18432
#define ATTN_SMEM_BYTES ((BUF0 + 2*BUFSZ) * 2)   // 110592

// bf16 hi/lo projected tensors (12 MB static scratch)
__device__ __nv_bfloat16 g_qh_hi[NT*HH], g_qh_lo[NT*HH];
__device__ __nv_bfloat16 g_kh_hi[NT*HH], g_kh_lo[NT*HH];
__device__ __nv_bfloat16 g_vt_hi[HH*NT], g_vt_lo[HH*NT];   // V transposed: [h][token]

// pre-converted weights, transposed [n][k] bf16 hi/lo
__device__ __nv_bfloat16 g_wt_hi[3][HH*DD], g_wt_lo[3][HH*DD];

// split-KV partials: unnormalized O + running max/sum per row
__device__ float g_po[2][NT*HH];
__device__ float g_pm[2][NT];
__device__ float g_pl[2][NT];

__device__ __forceinline__ uint32_t pack2(float lo, float hi) {
    uint32_t r;
    asm("cvt.rn.bf16x2.f32 %0, %1, %2;" : "=r"(r) : "f"(hi), "f"(lo));
    return r;
}
__device__ __forceinline__ void mma16816(float* d, uint32_t a0, uint32_t a1, uint32_t a2, uint32_t a3,
                                         uint32_t b0, uint32_t b1) {
    asm volatile("mma.sync.aligned.m16n8k16.row.col.f32.bf16.bf16.f32 "
        "{%0,%1,%2,%3}, {%4,%5,%6,%7}, {%8,%9}, {%0,%1,%2,%3};"
        : "+f"(d[0]), "+f"(d[1]), "+f"(d[2]), "+f"(d[3])
        : "r"(a0), "r"(a1), "r"(a2), "r"(a3), "r"(b0), "r"(b1));
}
__device__ __forceinline__ void cpa16(uint32_t dst, const void* src) {
    asm volatile("cp.async.cg.shared.global [%0], [%1], 16;" :: "r"(dst), "l"(src));
}
#define CPA_COMMIT() asm volatile("cp.async.commit_group;" ::: "memory")
#define CPA_WAIT(n)  asm volatile("cp.async.wait_group %0;" :: "n"(n) : "memory")

// ======================= W pre-conversion: [1024,64] -> [64][1024] bf16 hi/lo =======================
__global__ __launch_bounds__(256) void wconv_k(
    const float* __restrict__ Wq, const float* __restrict__ Wk, const float* __restrict__ Wv)
{
    const int gid = blockIdx.x * 256 + threadIdx.x;
    const int y = gid >> 16;
    const int rem = gid & 65535;
    const int n = rem >> 10, k = rem & 1023;
    const float* W = (y == 0) ? Wq : (y == 1) ? Wk : Wv;
    float w = W[(size_t)k * HH + n];
    __nv_bfloat16 bh = __float2bfloat16(w);
    g_wt_hi[y][(size_t)n * DD + k] = bh;
    g_wt_lo[y][(size_t)n * DD + k] = __float2bfloat16(w - __bfloat162float(bh));
}

// ======================= projection (unchanged from R8, 68-pad, uint32 STS) =======================
__global__ __launch_bounds__(256) void proj_tc(
    const float* __restrict__ q, const float* __restrict__ k, const float* __restrict__ v)
{
    extern __shared__ uint16_t psm[];
    uint16_t* Xhb[2] = {psm,         psm + 26112};
    uint16_t* Xlb[2] = {psm + 8704,  psm + 34816};
    uint16_t* Whb[2] = {psm + 17408, psm + 43520};
    uint16_t* Wlb[2] = {psm + 21760, psm + 47872};

    const int tid = threadIdx.x, wid = tid >> 5, lane = tid & 31;
    const int g = lane >> 2, t4 = lane & 3;
    const int y = blockIdx.y;
    const float* X = (y == 0) ? q : (y == 1) ? k : v;
    const __nv_bfloat16* gwh = g_wt_hi[y];
    const __nv_bfloat16* gwl = g_wt_lo[y];
    const int m0 = blockIdx.x * 128;
    const int rowA = (wid << 4) + g;

    float4 xv[8];
    uint4 wh4[2], wl4[2];

    auto load_regs = [&](int c0) {
        #pragma unroll
        for (int e = 0; e < 8; e++) {
            int idx = tid + 256 * e, r = idx >> 4, c4 = (idx & 15) << 2;
            xv[e] = *(const float4*)&X[(size_t)(m0 + r) * DD + c0 + c4];
        }
        #pragma unroll
        for (int e = 0; e < 2; e++) {
            int idx = tid + 256 * e, n = idx >> 3, k8 = (idx & 7) << 3;
            wh4[e] = *(const uint4*)&gwh[(size_t)n * DD + c0 + k8];
            wl4[e] = *(const uint4*)&gwl[(size_t)n * DD + c0 + k8];
        }
    };
    auto store_chunk = [&](int bb) {
        #pragma unroll
        for (int e = 0; e < 8; e++) {
            int idx = tid + 256 * e, r = idx >> 4, c4 = (idx & 15) << 2;
            float4 x = xv[e];
            uint32_t h01 = pack2(x.x, x.y), h23 = pack2(x.z, x.w);
            float hx = __uint_as_float(h01 << 16), hy = __uint_as_float(h01 & 0xffff0000u);
            float hz = __uint_as_float(h23 << 16), hw = __uint_as_float(h23 & 0xffff0000u);
            uint32_t l01 = pack2(x.x - hx, x.y - hy), l23 = pack2(x.z - hz, x.w - hw);
            *(uint32_t*)&Xhb[bb][r * 68 + c4]     = h01;
            *(uint32_t*)&Xhb[bb][r * 68 + c4 + 2] = h23;
            *(uint32_t*)&Xlb[bb][r * 68 + c4]     = l01;
            *(uint32_t*)&Xlb[bb][r * 68 + c4 + 2] = l23;
        }
        #pragma unroll
        for (int e = 0; e < 2; e++) {
            int idx = tid + 256 * e, n = idx >> 3, k8 = (idx & 7) << 3;
            const uint32_t* sh = (const uint32_t*)&wh4[e];
            const uint32_t* sl = (const uint32_t*)&wl4[e];
            #pragma unroll
            for (int u = 0; u < 4; u++) {
                *(uint32_t*)&Whb[bb][n * 68 + k8 + 2 * u] = sh[u];
                *(uint32_t*)&Wlb[bb][n * 68 + k8 + 2 * u] = sl[u];
            }
        }
    };

    float acc[8][4] = {};

    load_regs(0);
    store_chunk(0);
    __syncthreads();

    for (int c = 0; c < 16; c++) {
        const int cur = c & 1, nxt = cur ^ 1;
        const bool more = (c + 1 < 16);
        if (more) load_regs((c + 1) * 64);

        uint16_t* Xh = Xhb[cur]; uint16_t* Xl = Xlb[cur];
        uint16_t* Wh = Whb[cur]; uint16_t* Wl = Wlb[cur];
        #pragma unroll
        for (int cs = 0; cs < 4; cs++) {
            const int kc = cs * 16 + 2 * t4;
            uint32_t ah0 = *(uint32_t*)&Xh[rowA * 68 + kc],       ah1 = *(uint32_t*)&Xh[(rowA + 8) * 68 + kc];
            uint32_t ah2 = *(uint32_t*)&Xh[rowA * 68 + kc + 8],   ah3 = *(uint32_t*)&Xh[(rowA + 8) * 68 + kc + 8];
            uint32_t al0 = *(uint32_t*)&Xl[rowA * 68 + kc],       al1 = *(uint32_t*)&Xl[(rowA + 8) * 68 + kc];
            uint32_t al2 = *(uint32_t*)&Xl[rowA * 68 + kc + 8],   al3 = *(uint32_t*)&Xl[(rowA + 8) * 68 + kc + 8];
            #pragma unroll
            for (int j = 0; j < 8; j++) {
                int n = 8 * j + g;
                uint32_t bh0 = *(uint32_t*)&Wh[n * 68 + kc], bh1 = *(uint32_t*)&Wh[n * 68 + kc + 8];
                uint32_t bl0 = *(uint32_t*)&Wl[n * 68 + kc], bl1 = *(uint32_t*)&Wl[n * 68 + kc + 8];
                mma16816(acc[j], ah0, ah1, ah2, ah3, bh0, bh1);
                mma16816(acc[j], ah0, ah1, ah2, ah3, bl0, bl1);
                mma16816(acc[j], al0, al1, al2, al3, bh0, bh1);
            }
        }
        if (more) store_chunk(nxt);
        __syncthreads();
    }

    const int row0 = m0 + rowA;
    if (y < 2) {
        __nv_bfloat16* Oh = (y == 0) ? g_qh_hi : g_kh_hi;
        __nv_bfloat16* Ol = (y == 0) ? g_qh_lo : g_kh_lo;
        #pragma unroll
        for (int j = 0; j < 8; j++) {
            int col = 8 * j + 2 * t4;
            uint32_t hp0 = pack2(acc[j][0], acc[j][1]);
            float h0 = __uint_as_float(hp0 << 16), h1 = __uint_as_float(hp0 & 0xffff0000u);
            uint32_t lp0 = pack2(acc[j][0] - h0, acc[j][1] - h1);
            *(uint32_t*)&Oh[(size_t)row0 * HH + col] = hp0;
            *(uint32_t*)&Ol[(size_t)row0 * HH + col] = lp0;
            uint32_t hp1 = pack2(acc[j][2], acc[j][3]);
            float h2 = __uint_as_float(hp1 << 16), h3 = __uint_as_float(hp1 & 0xffff0000u);
            uint32_t lp1 = pack2(acc[j][2] - h2, acc[j][3] - h3);
            *(uint32_t*)&Oh[(size_t)(row0 + 8) * HH + col] = hp1;
            *(uint32_t*)&Ol[(size_t)(row0 + 8) * HH + col] = lp1;
        }
    } else {
        uint16_t* th = psm;
        uint16_t* tl = psm + 8192;
        #pragma unroll
        for (int j = 0; j < 8; j++) {
            int h = 8 * j + 2 * t4;
            #pragma unroll
            for (int e = 0; e < 4; e++) {
                int hc = h + (e & 1);
                int rr = rowA + ((e >= 2) ? 8 : 0);
                float val = acc[j][e];
                __nv_bfloat16 bh = __float2bfloat16(val);
                float res = val - __bfloat162float(bh);
                th[hc * 128 + rr] = __bfloat16_as_ushort(bh);
                tl[hc * 128 + rr] = __bfloat16_as_ushort(__float2bfloat16(res));
            }
        }
        __syncthreads();
        for (int i = tid; i < 1024; i += 256) {
            int h = i >> 4, c2 = i & 15;
            ((uint4*)(&g_vt_hi[(size_t)h * NT + m0]))[c2] = ((const uint4*)th)[h * 16 + c2];
            ((uint4*)(&g_vt_lo[(size_t)h * NT + m0]))[c2] = ((const uint4*)tl)[h * 16 + c2];
        }
    }
}

// ======================= flash attention: split-KV, cp.async 2-stage pipeline, 2 CTAs/SM =======================
// dynamic smem (uint16, APAD=72 rows): Qh@0(9216) Ql@9216 | buf0@18432: Kh(4608) Kl Vh Vl | buf1@36864
__global__ __launch_bounds__(256, 2) void attn_tc()
{
    extern __shared__ uint16_t sm[];
    uint16_t* Qh = sm;
    uint16_t* Ql = sm + QSZ;
    const uint32_t smb = (uint32_t)__cvta_generic_to_shared(sm);
    const int tid = threadIdx.x, wid = tid >> 5, lane = tid & 31;
    const int g = lane >> 2, t4 = lane & 3;
    const int b = blockIdx.y;
    const int qb = (NQB - 1) - (blockIdx.x >> 1);   // longest-first
    const int half = blockIdx.x & 1;
    const int q0 = qb * 128, bT = b * TT;
    const int rowA = (wid << 4) + g;
    const int tstart = half ? (qb + 1) : 0;
    const int tend   = half ? (2 * qb + 2) : (qb + 1);
    const int n = tend - tstart;

    // async-stage a K/V tile (bf16 hi/lo K + V^T) into buffer bb; all dsts 16B-aligned (APAD=72)
    auto issue_tile = [&](int k0n, int bb) {
        const uint32_t base = smb + (uint32_t)(BUF0 + bb * BUFSZ) * 2;
        #pragma unroll
        for (int e = 0; e < 8; e++) {
            int idx = tid + 256 * e;
            int arr = idx >> 9, w = idx & 511;
            int r = w >> 3, c8 = (w & 7) << 3;
            uint32_t dst = base + (uint32_t)(arr * TSZ + r * APAD + c8) * 2;
            const void* src;
            if (arr == 0)      src = &g_kh_hi[(size_t)(bT + k0n + r) * HH + c8];
            else if (arr == 1) src = &g_kh_lo[(size_t)(bT + k0n + r) * HH + c8];
            else if (arr == 2) src = &g_vt_hi[(size_t)r * NT + bT + k0n + c8];
            else               src = &g_vt_lo[(size_t)r * NT + bT + k0n + c8];
            cpa16(dst, src);
        }
        CPA_COMMIT();
    };

    // prologue: stage first two tiles async, then Q via plain loads (overlaps)
    issue_tile(tstart * 64, 0);
    if (n > 1) issue_tile((tstart + 1) * 64, 1);
    for (int i = tid; i < 2048; i += 256) {
        int r = i >> 4, c4 = (i & 15) << 2;
        *(uint2*)&Qh[r * APAD + c4] = *(const uint2*)&g_qh_hi[(size_t)(bT + q0 + r) * HH + c4];
        *(uint2*)&Ql[r * APAD + c4] = *(const uint2*)&g_qh_lo[(size_t)(bT + q0 + r) * HH + c4];
    }

    float oacc[8][4] = {};
    float m0r = MFLOOR, m1r = MFLOOR, l0r = 0.0f, l1r = 0.0f;

    for (int i = 0; i < n; i++) {
        const int tt = tstart + i;
        const int k0 = tt * 64;
        const int cur = i & 1;

        if (i <= n - 2) { CPA_WAIT(1); } else { CPA_WAIT(0); }
        __syncthreads();   // tile i visible to all threads

        uint16_t* Kh = sm + BUF0 + cur * BUFSZ;
        uint16_t* Kl = Kh + TSZ;
        uint16_t* Vh = Kh + 2 * TSZ;
        uint16_t* Vl = Kh + 3 * TSZ;

        // S = Q K^T (3 split terms)
        float sacc[8][4] = {};
        #pragma unroll
        for (int c = 0; c < 4; c++) {
            const int kc = 16 * c + 2 * t4;
            uint32_t ah0 = *(uint32_t*)&Qh[rowA * APAD + kc],       ah1 = *(uint32_t*)&Qh[(rowA + 8) * APAD + kc];
            uint32_t ah2 = *(uint32_t*)&Qh[rowA * APAD + kc + 8],   ah3 = *(uint32_t*)&Qh[(rowA + 8) * APAD + kc + 8];
            uint32_t al0 = *(uint32_t*)&Ql[rowA * APAD + kc],       al1 = *(uint32_t*)&Ql[(rowA + 8) * APAD + kc];
            uint32_t al2 = *(uint32_t*)&Ql[rowA * APAD + kc + 8],   al3 = *(uint32_t*)&Ql[(rowA + 8) * APAD + kc + 8];
            #pragma unroll
            for (int j = 0; j < 8; j++) {
                int nn = 8 * j + g;
                uint32_t bh0 = *(uint32_t*)&Kh[nn * APAD + kc], bh1 = *(uint32_t*)&Kh[nn * APAD + kc + 8];
                uint32_t bl0 = *(uint32_t*)&Kl[nn * APAD + kc], bl1 = *(uint32_t*)&Kl[nn * APAD + kc + 8];
                mma16816(sacc[j], ah0, ah1, ah2, ah3, bh0, bh1);
                mma16816(sacc[j], ah0, ah1, ah2, ah3, bl0, bl1);
                mma16816(sacc[j], al0, al1, al2, al3, bh0, bh1);
            }
        }

        // scale + causal mask: tile tt touches the diagonal iff tt >= 2*qb
        const bool domask = (tt >= 2 * qb);
        #pragma unroll
        for (int j = 0; j < 8; j++) {
            int col = k0 + 8 * j + 2 * t4;
            #pragma unroll
            for (int e = 0; e < 4; e++) {
                float val = sacc[j][e] * 0.125f;
                if (domask) {
                    int rr = q0 + rowA + ((e >= 2) ? 8 : 0);
                    if (col + (e & 1) > rr) val = NEGINF;
                }
                sacc[j][e] = val;
            }
        }

        // online softmax (finite floor)
        float mx0 = NEGINF, mx1 = NEGINF;
        #pragma unroll
        for (int j = 0; j < 8; j++) {
            mx0 = fmaxf(mx0, fmaxf(sacc[j][0], sacc[j][1]));
            mx1 = fmaxf(mx1, fmaxf(sacc[j][2], sacc[j][3]));
        }
        mx0 = fmaxf(mx0, __shfl_xor_sync(0xffffffffu, mx0, 1));
        mx0 = fmaxf(mx0, __shfl_xor_sync(0xffffffffu, mx0, 2));
        mx1 = fmaxf(mx1, __shfl_xor_sync(0xffffffffu, mx1, 1));
        mx1 = fmaxf(mx1, __shfl_xor_sync(0xffffffffu, mx1, 2));
        const float mn0 = fmaxf(m0r, mx0), mn1 = fmaxf(m1r, mx1);
        const float corr0 = __expf(m0r - mn0), corr1 = __expf(m1r - mn1);
        float s0 = 0.0f, s1 = 0.0f;
        #pragma unroll
        for (int j = 0; j < 8; j++) {
            float p0 = __expf(sacc[j][0] - mn0), p1 = __expf(sacc[j][1] - mn0);
            float p2 = __expf(sacc[j][2] - mn1), p3 = __expf(sacc[j][3] - mn1);
            sacc[j][0] = p0; sacc[j][1] = p1; sacc[j][2] = p2; sacc[j][3] = p3;
            s0 += p0 + p1; s1 += p2 + p3;
        }
        s0 += __shfl_xor_sync(0xffffffffu, s0, 1);
        s0 += __shfl_xor_sync(0xffffffffu, s0, 2);
        s1 += __shfl_xor_sync(0xffffffffu, s1, 1);
        s1 += __shfl_xor_sync(0xffffffffu, s1, 2);
        l0r = l0r * corr0 + s0; l1r = l1r * corr1 + s1;
        m0r = mn0; m1r = mn1;

        #pragma unroll
        for (int j = 0; j < 8; j++) {
            oacc[j][0] *= corr0; oacc[j][1] *= corr0;
            oacc[j][2] *= corr1; oacc[j][3] *= corr1;
        }

        // O += P V (P in registers)
        #pragma unroll
        for (int c = 0; c < 4; c++) {
            uint32_t ph0 = pack2(sacc[2*c][0],   sacc[2*c][1]);
            uint32_t ph1 = pack2(sacc[2*c][2],   sacc[2*c][3]);
            uint32_t ph2 = pack2(sacc[2*c+1][0], sacc[2*c+1][1]);
            uint32_t ph3 = pack2(sacc[2*c+1][2], sacc[2*c+1][3]);
            float r0 = sacc[2*c][0]   - __uint_as_float(ph0 << 16);
            float r1 = sacc[2*c][1]   - __uint_as_float(ph0 & 0xffff0000u);
            float r2 = sacc[2*c][2]   - __uint_as_float(ph1 << 16);
            float r3 = sacc[2*c][3]   - __uint_as_float(ph1 & 0xffff0000u);
            float r4 = sacc[2*c+1][0] - __uint_as_float(ph2 << 16);
            float r5 = sacc[2*c+1][1] - __uint_as_float(ph2 & 0xffff0000u);
            float r6 = sacc[2*c+1][2] - __uint_as_float(ph3 << 16);
            float r7 = sacc[2*c+1][3] - __uint_as_float(ph3 & 0xffff0000u);
            uint32_t pl0 = pack2(r0, r1), pl1 = pack2(r2, r3);
            uint32_t pl2 = pack2(r4, r5), pl3 = pack2(r6, r7);
            const int kc = 16 * c + 2 * t4;
            #pragma unroll
            for (int j2 = 0; j2 < 8; j2++) {
                int nn = 8 * j2 + g;
                uint32_t bh0 = *(uint32_t*)&Vh[nn * APAD + kc], bh1 = *(uint32_t*)&Vh[nn * APAD + kc + 8];
                uint32_t bl0 = *(uint32_t*)&Vl[nn * APAD + kc], bl1 = *(uint32_t*)&Vl[nn * APAD + kc + 8];
                mma16816(oacc[j2], ph0, ph1, ph2, ph3, bh0, bh1);
                mma16816(oacc[j2], ph0, ph1, ph2, ph3, bl0, bl1);
                mma16816(oacc[j2], pl0, pl1, pl2, pl3, bh0, bh1);
            }
        }

        // all warps done reading buffer `cur` -> safe to refill it with tile i+2
        __syncthreads();
        if (i + 2 < n) issue_tile((tt + 2) * 64, cur);
    }

    // store partials (unnormalized O, m, l)
    float* po = g_po[half];
    #pragma unroll
    for (int j = 0; j < 8; j++) {
        int col = 8 * j + 2 * t4;
        *(float2*)&po[(size_t)(bT + q0 + rowA) * HH + col] = make_float2(oacc[j][0], oacc[j][1]);
        *(float2*)&po[(size_t)(bT + q0 + rowA + 8) * HH + col] = make_float2(oacc[j][2], oacc[j][3]);
    }
    if (t4 == 0) {
        g_pm[half][bT + q0 + rowA] = m0r;      g_pl[half][bT + q0 + rowA] = l0r;
        g_pm[half][bT + q0 + rowA + 8] = m1r;  g_pl[half][bT + q0 + rowA + 8] = l1r;
    }
}

// ======================= merge the two split-KV partials =======================
__global__ __launch_bounds__(256) void merge_k(float* __restrict__ out)
{
    const int idx = blockIdx.x * 256 + threadIdx.x;
    const int row = idx >> 4;
    const int c4 = (idx & 15) << 2;
    const float m0 = g_pm[0][row], m1 = g_pm[1][row];
    const float ms = fmaxf(m0, m1);
    const float w0 = __expf(m0 - ms), w1 = __expf(m1 - ms);
    const float inv = 1.0f / (g_pl[0][row] * w0 + g_pl[1][row] * w1);
    const float4 a = *(const float4*)&g_po[0][(size_t)row * HH + c4];
    const float4 bq = *(const float4*)&g_po[1][(size_t)row * HH + c4];
    *(float4*)&out[(size_t)row * HH + c4] = make_float4(
        (a.x * w0 + bq.x * w1) * inv, (a.y * w0 + bq.y * w1) * inv,
        (a.z * w0 + bq.z * w1) * inv, (a.w * w0 + bq.w * w1) * inv);
}

extern "C" void kernel_launch(void* const* d_in, const int* in_sizes, int n_in,
                              void* d_out, int out_size)
{
    const float* q  = (const float*)d_in[0];
    const float* k  = (const float*)d_in[1];
    const float* v  = (const float*)d_in[2];
    const float* Wq = (const float*)d_in[3];
    const float* Wk = (const float*)d_in[4];
    const float* Wv = (const float*)d_in[5];
    // d_in[6] (tril mask) implemented analytically

    wconv_k<<<768, 256>>>(Wq, Wk, Wv);

    const int proj_smem = 104448;
    cudaFuncSetAttribute(proj_tc, cudaFuncAttributeMaxDynamicSharedMemorySize, proj_smem);
    proj_tc<<<dim3(NT / 128, 3), 256, proj_smem>>>(q, k, v);

    cudaFuncSetAttribute(attn_tc, cudaFuncAttributeMaxDynamicSharedMemorySize, ATTN_SMEM_BYTES);
    attn_tc<<<dim3(2 * NQB, BB), 256, ATTN_SMEM_BYTES>>>();

    merge_k<<<(NT * HH / 4) / 256, 256>>>((float*)d_out);
}

// round 13
// speedup vs baseline: 1.0065x; 1.0065x over previous
#include <cuda_runtime.h>
#include <cuda_bf16.h>
#include <cstdint>

#define BB 4
#define TT 4096
#define DD 1024
#define HH 64
#define NT (BB*TT)
#define NQB (TT/128)

#define NEGINF __int_as_float(0xff800000)
#define MFLOOR (-1e30f)

// attn smem geometry (uint16 units): row pad 72 (144 B, 16B-aligned rows for cp.async)
#define APAD 72
#define QSZ  (128*APAD)
#define TSZ  (64*APAD)
#define BUF0 (2*QSZ)
#define BUFSZ (4*TSZ)
#define ATTN_SMEM_BYTES ((BUF0 + 2*BUFSZ) * 2)   // 110592

__device__ __nv_bfloat16 g_qh_hi[NT*HH], g_qh_lo[NT*HH];
__device__ __nv_bfloat16 g_kh_hi[NT*HH], g_kh_lo[NT*HH];
__device__ __nv_bfloat16 g_vt_hi[HH*NT], g_vt_lo[HH*NT];
__device__ __nv_bfloat16 g_wt_hi[3][HH*DD], g_wt_lo[3][HH*DD];
__device__ float g_po[2][NT*HH];
__device__ float g_pm[2][NT];
__device__ float g_pl[2][NT];

__device__ __forceinline__ uint32_t pack2(float lo, float hi) {
    uint32_t r;
    asm("cvt.rn.bf16x2.f32 %0, %1, %2;" : "=r"(r) : "f"(hi), "f"(lo));
    return r;
}
// volatile (proven-stable build path); independence is expressed by source order:
// each pass iterates 8 distinct accumulators, so dependent reuse is >= 8 MMAs apart.
__device__ __forceinline__ void mma16816(float* d, uint32_t a0, uint32_t a1, uint32_t a2, uint32_t a3,
                                         uint32_t b0, uint32_t b1) {
    asm volatile("mma.sync.aligned.m16n8k16.row.col.f32.bf16.bf16.f32 "
        "{%0,%1,%2,%3}, {%4,%5,%6,%7}, {%8,%9}, {%0,%1,%2,%3};"
        : "+f"(d[0]), "+f"(d[1]), "+f"(d[2]), "+f"(d[3])
        : "r"(a0), "r"(a1), "r"(a2), "r"(a3), "r"(b0), "r"(b1));
}
__device__ __forceinline__ void cpa16(uint32_t dst, const void* src) {
    asm volatile("cp.async.cg.shared.global [%0], [%1], 16;" :: "r"(dst), "l"(src));
}
#define CPA_COMMIT() asm volatile("cp.async.commit_group;" ::: "memory")
#define CPA_WAIT(n)  asm volatile("cp.async.wait_group %0;" :: "n"(n) : "memory")

// ======================= W pre-conversion =======================
__global__ __launch_bounds__(256) void wconv_k(
    const float* __restrict__ Wq, const float* __restrict__ Wk, const float* __restrict__ Wv)
{
    const int gid = blockIdx.x * 256 + threadIdx.x;
    const int y = gid >> 16;
    const int rem = gid & 65535;
    const int n = rem >> 10, k = rem & 1023;
    const float* W = (y == 0) ? Wq : (y == 1) ? Wk : Wv;
    float w = W[(size_t)k * HH + n];
    __nv_bfloat16 bh = __float2bfloat16(w);
    g_wt_hi[y][(size_t)n * DD + k] = bh;
    g_wt_lo[y][(size_t)n * DD + k] = __float2bfloat16(w - __bfloat162float(bh));
}

// ======================= projection: term-major MMA passes =======================
__global__ __launch_bounds__(256) void proj_tc(
    const float* __restrict__ q, const float* __restrict__ k, const float* __restrict__ v)
{
    extern __shared__ uint16_t psm[];
    uint16_t* Xhb[2] = {psm,         psm + 26112};
    uint16_t* Xlb[2] = {psm + 8704,  psm + 34816};
    uint16_t* Whb[2] = {psm + 17408, psm + 43520};
    uint16_t* Wlb[2] = {psm + 21760, psm + 47872};

    const int tid = threadIdx.x, wid = tid >> 5, lane = tid & 31;
    const int g = lane >> 2, t4 = lane & 3;
    const int y = blockIdx.y;
    const float* X = (y == 0) ? q : (y == 1) ? k : v;
    const __nv_bfloat16* gwh = g_wt_hi[y];
    const __nv_bfloat16* gwl = g_wt_lo[y];
    const int m0 = blockIdx.x * 128;
    const int rowA = (wid << 4) + g;

    float4 xv[8];
    uint4 wh4[2], wl4[2];

    auto load_regs = [&](int c0) {
        #pragma unroll
        for (int e = 0; e < 8; e++) {
            int idx = tid + 256 * e, r = idx >> 4, c4 = (idx & 15) << 2;
            xv[e] = *(const float4*)&X[(size_t)(m0 + r) * DD + c0 + c4];
        }
        #pragma unroll
        for (int e = 0; e < 2; e++) {
            int idx = tid + 256 * e, n = idx >> 3, k8 = (idx & 7) << 3;
            wh4[e] = *(const uint4*)&gwh[(size_t)n * DD + c0 + k8];
            wl4[e] = *(const uint4*)&gwl[(size_t)n * DD + c0 + k8];
        }
    };
    auto store_chunk = [&](int bb) {
        #pragma unroll
        for (int e = 0; e < 8; e++) {
            int idx = tid + 256 * e, r = idx >> 4, c4 = (idx & 15) << 2;
            float4 x = xv[e];
            uint32_t h01 = pack2(x.x, x.y), h23 = pack2(x.z, x.w);
            float hx = __uint_as_float(h01 << 16), hy = __uint_as_float(h01 & 0xffff0000u);
            float hz = __uint_as_float(h23 << 16), hw = __uint_as_float(h23 & 0xffff0000u);
            uint32_t l01 = pack2(x.x - hx, x.y - hy), l23 = pack2(x.z - hz, x.w - hw);
            *(uint32_t*)&Xhb[bb][r * 68 + c4]     = h01;
            *(uint32_t*)&Xhb[bb][r * 68 + c4 + 2] = h23;
            *(uint32_t*)&Xlb[bb][r * 68 + c4]     = l01;
            *(uint32_t*)&Xlb[bb][r * 68 + c4 + 2] = l23;
        }
        #pragma unroll
        for (int e = 0; e < 2; e++) {
            int idx = tid + 256 * e, n = idx >> 3, k8 = (idx & 7) << 3;
            const uint32_t* sh = (const uint32_t*)&wh4[e];
            const uint32_t* sl = (const uint32_t*)&wl4[e];
            #pragma unroll
            for (int u = 0; u < 4; u++) {
                *(uint32_t*)&Whb[bb][n * 68 + k8 + 2 * u] = sh[u];
                *(uint32_t*)&Wlb[bb][n * 68 + k8 + 2 * u] = sl[u];
            }
        }
    };

    float acc[8][4] = {};

    load_regs(0);
    store_chunk(0);
    __syncthreads();

    for (int c = 0; c < 16; c++) {
        const int cur = c & 1, nxt = cur ^ 1;
        const bool more = (c + 1 < 16);
        if (more) load_regs((c + 1) * 64);

        uint16_t* Xh = Xhb[cur]; uint16_t* Xl = Xlb[cur];
        uint16_t* Wh = Whb[cur]; uint16_t* Wl = Wlb[cur];
        #pragma unroll
        for (int cs = 0; cs < 4; cs++) {
            const int kc = cs * 16 + 2 * t4;
            uint32_t ah0 = *(uint32_t*)&Xh[rowA * 68 + kc],       ah1 = *(uint32_t*)&Xh[(rowA + 8) * 68 + kc];
            uint32_t ah2 = *(uint32_t*)&Xh[rowA * 68 + kc + 8],   ah3 = *(uint32_t*)&Xh[(rowA + 8) * 68 + kc + 8];
            uint32_t al0 = *(uint32_t*)&Xl[rowA * 68 + kc],       al1 = *(uint32_t*)&Xl[(rowA + 8) * 68 + kc];
            uint32_t al2 = *(uint32_t*)&Xl[rowA * 68 + kc + 8],   al3 = *(uint32_t*)&Xl[(rowA + 8) * 68 + kc + 8];
            // pass 1: hh — 8 independent accumulators back-to-back
            #pragma unroll
            for (int j = 0; j < 8; j++) {
                int n = 8 * j + g;
                mma16816(acc[j], ah0, ah1, ah2, ah3,
                         *(uint32_t*)&Wh[n * 68 + kc], *(uint32_t*)&Wh[n * 68 + kc + 8]);
            }
            // pass 2: lh
            #pragma unroll
            for (int j = 0; j < 8; j++) {
                int n = 8 * j + g;
                mma16816(acc[j], al0, al1, al2, al3,
                         *(uint32_t*)&Wh[n * 68 + kc], *(uint32_t*)&Wh[n * 68 + kc + 8]);
            }
            // pass 3: hl
            #pragma unroll
            for (int j = 0; j < 8; j++) {
                int n = 8 * j + g;
                mma16816(acc[j], ah0, ah1, ah2, ah3,
                         *(uint32_t*)&Wl[n * 68 + kc], *(uint32_t*)&Wl[n * 68 + kc + 8]);
            }
        }
        if (more) store_chunk(nxt);
        __syncthreads();
    }

    const int row0 = m0 + rowA;
    if (y < 2) {
        __nv_bfloat16* Oh = (y == 0) ? g_qh_hi : g_kh_hi;
        __nv_bfloat16* Ol = (y == 0) ? g_qh_lo : g_kh_lo;
        #pragma unroll
        for (int j = 0; j < 8; j++) {
            int col = 8 * j + 2 * t4;
            uint32_t hp0 = pack2(acc[j][0], acc[j][1]);
            float h0 = __uint_as_float(hp0 << 16), h1 = __uint_as_float(hp0 & 0xffff0000u);
            uint32_t lp0 = pack2(acc[j][0] - h0, acc[j][1] - h1);
            *(uint32_t*)&Oh[(size_t)row0 * HH + col] = hp0;
            *(uint32_t*)&Ol[(size_t)row0 * HH + col] = lp0;
            uint32_t hp1 = pack2(acc[j][2], acc[j][3]);
            float h2 = __uint_as_float(hp1 << 16), h3 = __uint_as_float(hp1 & 0xffff0000u);
            uint32_t lp1 = pack2(acc[j][2] - h2, acc[j][3] - h3);
            *(uint32_t*)&Oh[(size_t)(row0 + 8) * HH + col] = hp1;
            *(uint32_t*)&Ol[(size_t)(row0 + 8) * HH + col] = lp1;
        }
    } else {
        uint16_t* th = psm;
        uint16_t* tl = psm + 8192;
        #pragma unroll
        for (int j = 0; j < 8; j++) {
            int h = 8 * j + 2 * t4;
            #pragma unroll
            for (int e = 0; e < 4; e++) {
                int hc = h + (e & 1);
                int rr = rowA + ((e >= 2) ? 8 : 0);
                float val = acc[j][e];
                __nv_bfloat16 bh = __float2bfloat16(val);
                float res = val - __bfloat162float(bh);
                th[hc * 128 + rr] = __bfloat16_as_ushort(bh);
                tl[hc * 128 + rr] = __bfloat16_as_ushort(__float2bfloat16(res));
            }
        }
        __syncthreads();
        for (int i = tid; i < 1024; i += 256) {
            int h = i >> 4, c2 = i & 15;
            ((uint4*)(&g_vt_hi[(size_t)h * NT + m0]))[c2] = ((const uint4*)th)[h * 16 + c2];
            ((uint4*)(&g_vt_lo[(size_t)h * NT + m0]))[c2] = ((const uint4*)tl)[h * 16 + c2];
        }
    }
}

// ======================= flash attention: split-KV, cp.async, term-major MMA =======================
__global__ __launch_bounds__(256, 2) void attn_tc()
{
    extern __shared__ uint16_t sm[];
    uint16_t* Qh = sm;
    uint16_t* Ql = sm + QSZ;
    const uint32_t smb = (uint32_t)__cvta_generic_to_shared(sm);
    const int tid = threadIdx.x, wid = tid >> 5, lane = tid & 31;
    const int g = lane >> 2, t4 = lane & 3;
    const int b = blockIdx.y;
    const int qb = (NQB - 1) - (blockIdx.x >> 1);
    const int half = blockIdx.x & 1;
    const int q0 = qb * 128, bT = b * TT;
    const int rowA = (wid << 4) + g;
    const int tstart = half ? (qb + 1) : 0;
    const int tend   = half ? (2 * qb + 2) : (qb + 1);
    const int n = tend - tstart;

    auto issue_tile = [&](int k0n, int bb) {
        const uint32_t base = smb + (uint32_t)(BUF0 + bb * BUFSZ) * 2;
        #pragma unroll
        for (int e = 0; e < 8; e++) {
            int idx = tid + 256 * e;
            int arr = idx >> 9, w = idx & 511;
            int r = w >> 3, c8 = (w & 7) << 3;
            uint32_t dst = base + (uint32_t)(arr * TSZ + r * APAD + c8) * 2;
            const void* src;
            if (arr == 0)      src = &g_kh_hi[(size_t)(bT + k0n + r) * HH + c8];
            else if (arr == 1) src = &g_kh_lo[(size_t)(bT + k0n + r) * HH + c8];
            else if (arr == 2) src = &g_vt_hi[(size_t)r * NT + bT + k0n + c8];
            else               src = &g_vt_lo[(size_t)r * NT + bT + k0n + c8];
            cpa16(dst, src);
        }
        CPA_COMMIT();
    };

    issue_tile(tstart * 64, 0);
    if (n > 1) issue_tile((tstart + 1) * 64, 1);
    for (int i = tid; i < 2048; i += 256) {
        int r = i >> 4, c4 = (i & 15) << 2;
        *(uint2*)&Qh[r * APAD + c4] = *(const uint2*)&g_qh_hi[(size_t)(bT + q0 + r) * HH + c4];
        *(uint2*)&Ql[r * APAD + c4] = *(const uint2*)&g_qh_lo[(size_t)(bT + q0 + r) * HH + c4];
    }

    float oacc[8][4] = {};
    float m0r = MFLOOR, m1r = MFLOOR, l0r = 0.0f, l1r = 0.0f;

    for (int i = 0; i < n; i++) {
        const int tt = tstart + i;
        const int k0 = tt * 64;
        const int cur = i & 1;

        if (i <= n - 2) { CPA_WAIT(1); } else { CPA_WAIT(0); }
        __syncthreads();

        uint16_t* Kh = sm + BUF0 + cur * BUFSZ;
        uint16_t* Kl = Kh + TSZ;
        uint16_t* Vh = Kh + 2 * TSZ;
        uint16_t* Vl = Kh + 3 * TSZ;

        // S = Q K^T : term-major passes (8 independent accumulators per pass)
        float sacc[8][4] = {};
        #pragma unroll
        for (int c = 0; c < 4; c++) {
            const int kc = 16 * c + 2 * t4;
            uint32_t ah0 = *(uint32_t*)&Qh[rowA * APAD + kc],       ah1 = *(uint32_t*)&Qh[(rowA + 8) * APAD + kc];
            uint32_t ah2 = *(uint32_t*)&Qh[rowA * APAD + kc + 8],   ah3 = *(uint32_t*)&Qh[(rowA + 8) * APAD + kc + 8];
            uint32_t al0 = *(uint32_t*)&Ql[rowA * APAD + kc],       al1 = *(uint32_t*)&Ql[(rowA + 8) * APAD + kc];
            uint32_t al2 = *(uint32_t*)&Ql[rowA * APAD + kc + 8],   al3 = *(uint32_t*)&Ql[(rowA + 8) * APAD + kc + 8];
            #pragma unroll
            for (int j = 0; j < 8; j++) {
                int nn = 8 * j + g;
                mma16816(sacc[j], ah0, ah1, ah2, ah3,
                         *(uint32_t*)&Kh[nn * APAD + kc], *(uint32_t*)&Kh[nn * APAD + kc + 8]);
            }
            #pragma unroll
            for (int j = 0; j < 8; j++) {
                int nn = 8 * j + g;
                mma16816(sacc[j], al0, al1, al2, al3,
                         *(uint32_t*)&Kh[nn * APAD + kc], *(uint32_t*)&Kh[nn * APAD + kc + 8]);
            }
            #pragma unroll
            for (int j = 0; j < 8; j++) {
                int nn = 8 * j + g;
                mma16816(sacc[j], ah0, ah1, ah2, ah3,
                         *(uint32_t*)&Kl[nn * APAD + kc], *(uint32_t*)&Kl[nn * APAD + kc + 8]);
            }
        }

        // scale + causal mask
        const bool domask = (tt >= 2 * qb);
        #pragma unroll
        for (int j = 0; j < 8; j++) {
            int col = k0 + 8 * j + 2 * t4;
            #pragma unroll
            for (int e = 0; e < 4; e++) {
                float val = sacc[j][e] * 0.125f;
                if (domask) {
                    int rr = q0 + rowA + ((e >= 2) ? 8 : 0);
                    if (col + (e & 1) > rr) val = NEGINF;
                }
                sacc[j][e] = val;
            }
        }

        // online softmax (finite floor)
        float mx0 = NEGINF, mx1 = NEGINF;
        #pragma unroll
        for (int j = 0; j < 8; j++) {
            mx0 = fmaxf(mx0, fmaxf(sacc[j][0], sacc[j][1]));
            mx1 = fmaxf(mx1, fmaxf(sacc[j][2], sacc[j][3]));
        }
        mx0 = fmaxf(mx0, __shfl_xor_sync(0xffffffffu, mx0, 1));
        mx0 = fmaxf(mx0, __shfl_xor_sync(0xffffffffu, mx0, 2));
        mx1 = fmaxf(mx1, __shfl_xor_sync(0xffffffffu, mx1, 1));
        mx1 = fmaxf(mx1, __shfl_xor_sync(0xffffffffu, mx1, 2));
        const float mn0 = fmaxf(m0r, mx0), mn1 = fmaxf(m1r, mx1);
        const float corr0 = __expf(m0r - mn0), corr1 = __expf(m1r - mn1);
        float s0 = 0.0f, s1 = 0.0f;
        #pragma unroll
        for (int j = 0; j < 8; j++) {
            float p0 = __expf(sacc[j][0] - mn0), p1 = __expf(sacc[j][1] - mn0);
            float p2 = __expf(sacc[j][2] - mn1), p3 = __expf(sacc[j][3] - mn1);
            sacc[j][0] = p0; sacc[j][1] = p1; sacc[j][2] = p2; sacc[j][3] = p3;
            s0 += p0 + p1; s1 += p2 + p3;
        }
        s0 += __shfl_xor_sync(0xffffffffu, s0, 1);
        s0 += __shfl_xor_sync(0xffffffffu, s0, 2);
        s1 += __shfl_xor_sync(0xffffffffu, s1, 1);
        s1 += __shfl_xor_sync(0xffffffffu, s1, 2);
        l0r = l0r * corr0 + s0; l1r = l1r * corr1 + s1;
        m0r = mn0; m1r = mn1;

        #pragma unroll
        for (int j = 0; j < 8; j++) {
            oacc[j][0] *= corr0; oacc[j][1] *= corr0;
            oacc[j][2] *= corr1; oacc[j][3] *= corr1;
        }

        // O += P V : pack P per c-slice, then term-major passes
        #pragma unroll
        for (int c = 0; c < 4; c++) {
            uint32_t ph0 = pack2(sacc[2*c][0],   sacc[2*c][1]);
            uint32_t ph1 = pack2(sacc[2*c][2],   sacc[2*c][3]);
            uint32_t ph2 = pack2(sacc[2*c+1][0], sacc[2*c+1][1]);
            uint32_t ph3 = pack2(sacc[2*c+1][2], sacc[2*c+1][3]);
            float r0 = sacc[2*c][0]   - __uint_as_float(ph0 << 16);
            float r1 = sacc[2*c][1]   - __uint_as_float(ph0 & 0xffff0000u);
            float r2 = sacc[2*c][2]   - __uint_as_float(ph1 << 16);
            float r3 = sacc[2*c][3]   - __uint_as_float(ph1 & 0xffff0000u);
            float r4 = sacc[2*c+1][0] - __uint_as_float(ph2 << 16);
            float r5 = sacc[2*c+1][1] - __uint_as_float(ph2 & 0xffff0000u);
            float r6 = sacc[2*c+1][2] - __uint_as_float(ph3 << 16);
            float r7 = sacc[2*c+1][3] - __uint_as_float(ph3 & 0xffff0000u);
            uint32_t pl0 = pack2(r0, r1), pl1 = pack2(r2, r3);
            uint32_t pl2 = pack2(r4, r5), pl3 = pack2(r6, r7);
            const int kc = 16 * c + 2 * t4;
            #pragma unroll
            for (int j2 = 0; j2 < 8; j2++) {
                int nn = 8 * j2 + g;
                mma16816(oacc[j2], ph0, ph1, ph2, ph3,
                         *(uint32_t*)&Vh[nn * APAD + kc], *(uint32_t*)&Vh[nn * APAD + kc + 8]);
            }
            #pragma unroll
            for (int j2 = 0; j2 < 8; j2++) {
                int nn = 8 * j2 + g;
                mma16816(oacc[j2], pl0, pl1, pl2, pl3,
                         *(uint32_t*)&Vh[nn * APAD + kc], *(uint32_t*)&Vh[nn * APAD + kc + 8]);
            }
            #pragma unroll
            for (int j2 = 0; j2 < 8; j2++) {
                int nn = 8 * j2 + g;
                mma16816(oacc[j2], ph0, ph1, ph2, ph3,
                         *(uint32_t*)&Vl[nn * APAD + kc], *(uint32_t*)&Vl[nn * APAD + kc + 8]);
            }
        }

        __syncthreads();
        if (i + 2 < n) issue_tile((tt + 2) * 64, cur);
    }

    float* po = g_po[half];
    #pragma unroll
    for (int j = 0; j < 8; j++) {
        int col = 8 * j + 2 * t4;
        *(float2*)&po[(size_t)(bT + q0 + rowA) * HH + col] = make_float2(oacc[j][0], oacc[j][1]);
        *(float2*)&po[(size_t)(bT + q0 + rowA + 8) * HH + col] = make_float2(oacc[j][2], oacc[j][3]);
    }
    if (t4 == 0) {
        g_pm[half][bT + q0 + rowA] = m0r;      g_pl[half][bT + q0 + rowA] = l0r;
        g_pm[half][bT + q0 + rowA + 8] = m1r;  g_pl[half][bT + q0 + rowA + 8] = l1r;
    }
}

// ======================= merge =======================
__global__ __launch_bounds__(256) void merge_k(float* __restrict__ out)
{
    const int idx = blockIdx.x * 256 + threadIdx.x;
    const int row = idx >> 4;
    const int c4 = (idx & 15) << 2;
    const float m0 = g_pm[0][row], m1 = g_pm[1][row];
    const float ms = fmaxf(m0, m1);
    const float w0 = __expf(m0 - ms), w1 = __expf(m1 - ms);
    const float inv = 1.0f / (g_pl[0][row] * w0 + g_pl[1][row] * w1);
    const float4 a = *(const float4*)&g_po[0][(size_t)row * HH + c4];
    const float4 bq = *(const float4*)&g_po[1][(size_t)row * HH + c4];
    *(float4*)&out[(size_t)row * HH + c4] = make_float4(
        (a.x * w0 + bq.x * w1) * inv, (a.y * w0 + bq.y * w1) * inv,
        (a.z * w0 + bq.z * w1) * inv, (a.w * w0 + bq.w * w1) * inv);
}

extern "C" void kernel_launch(void* const* d_in, const int* in_sizes, int n_in,
                              void* d_out, int out_size)
{
    const float* q  = (const float*)d_in[0];
    const float* k  = (const float*)d_in[1];
    const float* v  = (const float*)d_in[2];
    const float* Wq = (const float*)d_in[3];
    const float* Wk = (const float*)d_in[4];
    const float* Wv = (const float*)d_in[5];
    // d_in[6] (tril mask) implemented analytically

    wconv_k<<<768, 256>>>(Wq, Wk, Wv);

    const int proj_smem = 104448;
    cudaFuncSetAttribute(proj_tc, cudaFuncAttributeMaxDynamicSharedMemorySize, proj_smem);
    proj_tc<<<dim3(NT / 128, 3), 256, proj_smem>>>(q, k, v);

    cudaFuncSetAttribute(attn_tc, cudaFuncAttributeMaxDynamicSharedMemorySize, ATTN_SMEM_BYTES);
    attn_tc<<<dim3(2 * NQB, BB), 256, ATTN_SMEM_BYTES>>>();

    merge_k<<<(NT * HH / 4) / 256, 256>>>((float*)d_out);
}

// round 14
// speedup vs baseline: 1.1427x; 1.1353x over previous
#include <cuda_runtime.h>
#include <cuda_bf16.h>
#include <cstdint>

#define BB 4
#define TT 4096
#define DD 1024
#define HH 64
#define NT (BB*TT)
#define NQB (TT/128)

#define NEGINF __int_as_float(0xff800000)
#define MFLOOR (-1e30f)

// attn smem geometry (uint16 units): row pad 72 (144 B, 16B-aligned rows for cp.async)
#define APAD 72
#define QSZ  (128*APAD)
#define TSZ  (64*APAD)
#define BUF0 (2*QSZ)
#define BUFSZ (4*TSZ)
#define ATTN_SMEM_BYTES ((BUF0 + 2*BUFSZ) * 2)   // 110592

__device__ __nv_bfloat16 g_qh_hi[NT*HH], g_qh_lo[NT*HH];
__device__ __nv_bfloat16 g_kh_hi[NT*HH], g_kh_lo[NT*HH];
__device__ __nv_bfloat16 g_vt_hi[HH*NT], g_vt_lo[HH*NT];
__device__ __nv_bfloat16 g_wt_hi[3][HH*DD], g_wt_lo[3][HH*DD];
__device__ float g_po[2][NT*HH];
__device__ float g_pm[2][NT];
__device__ float g_pl[2][NT];

__device__ __forceinline__ uint32_t pack2(float lo, float hi) {
    uint32_t r;
    asm("cvt.rn.bf16x2.f32 %0, %1, %2;" : "=r"(r) : "f"(hi), "f"(lo));
    return r;
}
__device__ __forceinline__ void mma16816(float* d, uint32_t a0, uint32_t a1, uint32_t a2, uint32_t a3,
                                         uint32_t b0, uint32_t b1) {
    asm volatile("mma.sync.aligned.m16n8k16.row.col.f32.bf16.bf16.f32 "
        "{%0,%1,%2,%3}, {%4,%5,%6,%7}, {%8,%9}, {%0,%1,%2,%3};"
        : "+f"(d[0]), "+f"(d[1]), "+f"(d[2]), "+f"(d[3])
        : "r"(a0), "r"(a1), "r"(a2), "r"(a3), "r"(b0), "r"(b1));
}
__device__ __forceinline__ void cpa16(uint32_t dst, const void* src) {
    asm volatile("cp.async.cg.shared.global [%0], [%1], 16;" :: "r"(dst), "l"(src));
}
#define CPA_COMMIT() asm volatile("cp.async.commit_group;" ::: "memory")
#define CPA_WAIT(n)  asm volatile("cp.async.wait_group %0;" :: "n"(n) : "memory")

// ======================= W pre-conversion =======================
__global__ __launch_bounds__(256) void wconv_k(
    const float* __restrict__ Wq, const float* __restrict__ Wk, const float* __restrict__ Wv)
{
    const int gid = blockIdx.x * 256 + threadIdx.x;
    const int y = gid >> 16;
    const int rem = gid & 65535;
    const int n = rem >> 10, k = rem & 1023;
    const float* W = (y == 0) ? Wq : (y == 1) ? Wk : Wv;
    float w = W[(size_t)k * HH + n];
    __nv_bfloat16 bh = __float2bfloat16(w);
    g_wt_hi[y][(size_t)n * DD + k] = bh;
    g_wt_lo[y][(size_t)n * DD + k] = __float2bfloat16(w - __bfloat162float(bh));
}

// ======================= projection (unchanged from R13) =======================
__global__ __launch_bounds__(256) void proj_tc(
    const float* __restrict__ q, const float* __restrict__ k, const float* __restrict__ v)
{
    extern __shared__ uint16_t psm[];
    uint16_t* Xhb[2] = {psm,         psm + 26112};
    uint16_t* Xlb[2] = {psm + 8704,  psm + 34816};
    uint16_t* Whb[2] = {psm + 17408, psm + 43520};
    uint16_t* Wlb[2] = {psm + 21760, psm + 47872};

    const int tid = threadIdx.x, wid = tid >> 5, lane = tid & 31;
    const int g = lane >> 2, t4 = lane & 3;
    const int y = blockIdx.y;
    const float* X = (y == 0) ? q : (y == 1) ? k : v;
    const __nv_bfloat16* gwh = g_wt_hi[y];
    const __nv_bfloat16* gwl = g_wt_lo[y];
    const int m0 = blockIdx.x * 128;
    const int rowA = (wid << 4) + g;

    float4 xv[8];
    uint4 wh4[2], wl4[2];

    auto load_regs = [&](int c0) {
        #pragma unroll
        for (int e = 0; e < 8; e++) {
            int idx = tid + 256 * e, r = idx >> 4, c4 = (idx & 15) << 2;
            xv[e] = *(const float4*)&X[(size_t)(m0 + r) * DD + c0 + c4];
        }
        #pragma unroll
        for (int e = 0; e < 2; e++) {
            int idx = tid + 256 * e, n = idx >> 3, k8 = (idx & 7) << 3;
            wh4[e] = *(const uint4*)&gwh[(size_t)n * DD + c0 + k8];
            wl4[e] = *(const uint4*)&gwl[(size_t)n * DD + c0 + k8];
        }
    };
    auto store_chunk = [&](int bb) {
        #pragma unroll
        for (int e = 0; e < 8; e++) {
            int idx = tid + 256 * e, r = idx >> 4, c4 = (idx & 15) << 2;
            float4 x = xv[e];
            uint32_t h01 = pack2(x.x, x.y), h23 = pack2(x.z, x.w);
            float hx = __uint_as_float(h01 << 16), hy = __uint_as_float(h01 & 0xffff0000u);
            float hz = __uint_as_float(h23 << 16), hw = __uint_as_float(h23 & 0xffff0000u);
            uint32_t l01 = pack2(x.x - hx, x.y - hy), l23 = pack2(x.z - hz, x.w - hw);
            *(uint32_t*)&Xhb[bb][r * 68 + c4]     = h01;
            *(uint32_t*)&Xhb[bb][r * 68 + c4 + 2] = h23;
            *(uint32_t*)&Xlb[bb][r * 68 + c4]     = l01;
            *(uint32_t*)&Xlb[bb][r * 68 + c4 + 2] = l23;
        }
        #pragma unroll
        for (int e = 0; e < 2; e++) {
            int idx = tid + 256 * e, n = idx >> 3, k8 = (idx & 7) << 3;
            const uint32_t* sh = (const uint32_t*)&wh4[e];
            const uint32_t* sl = (const uint32_t*)&wl4[e];
            #pragma unroll
            for (int u = 0; u < 4; u++) {
                *(uint32_t*)&Whb[bb][n * 68 + k8 + 2 * u] = sh[u];
                *(uint32_t*)&Wlb[bb][n * 68 + k8 + 2 * u] = sl[u];
            }
        }
    };

    float acc[8][4] = {};

    load_regs(0);
    store_chunk(0);
    __syncthreads();

    for (int c = 0; c < 16; c++) {
        const int cur = c & 1, nxt = cur ^ 1;
        const bool more = (c + 1 < 16);
        if (more) load_regs((c + 1) * 64);

        uint16_t* Xh = Xhb[cur]; uint16_t* Xl = Xlb[cur];
        uint16_t* Wh = Whb[cur]; uint16_t* Wl = Wlb[cur];
        #pragma unroll
        for (int cs = 0; cs < 4; cs++) {
            const int kc = cs * 16 + 2 * t4;
            uint32_t ah0 = *(uint32_t*)&Xh[rowA * 68 + kc],       ah1 = *(uint32_t*)&Xh[(rowA + 8) * 68 + kc];
            uint32_t ah2 = *(uint32_t*)&Xh[rowA * 68 + kc + 8],   ah3 = *(uint32_t*)&Xh[(rowA + 8) * 68 + kc + 8];
            uint32_t al0 = *(uint32_t*)&Xl[rowA * 68 + kc],       al1 = *(uint32_t*)&Xl[(rowA + 8) * 68 + kc];
            uint32_t al2 = *(uint32_t*)&Xl[rowA * 68 + kc + 8],   al3 = *(uint32_t*)&Xl[(rowA + 8) * 68 + kc + 8];
            #pragma unroll
            for (int j = 0; j < 8; j++) {
                int n = 8 * j + g;
                mma16816(acc[j], ah0, ah1, ah2, ah3,
                         *(uint32_t*)&Wh[n * 68 + kc], *(uint32_t*)&Wh[n * 68 + kc + 8]);
            }
            #pragma unroll
            for (int j = 0; j < 8; j++) {
                int n = 8 * j + g;
                mma16816(acc[j], al0, al1, al2, al3,
                         *(uint32_t*)&Wh[n * 68 + kc], *(uint32_t*)&Wh[n * 68 + kc + 8]);
            }
            #pragma unroll
            for (int j = 0; j < 8; j++) {
                int n = 8 * j + g;
                mma16816(acc[j], ah0, ah1, ah2, ah3,
                         *(uint32_t*)&Wl[n * 68 + kc], *(uint32_t*)&Wl[n * 68 + kc + 8]);
            }
        }
        if (more) store_chunk(nxt);
        __syncthreads();
    }

    const int row0 = m0 + rowA;
    if (y < 2) {
        __nv_bfloat16* Oh = (y == 0) ? g_qh_hi : g_kh_hi;
        __nv_bfloat16* Ol = (y == 0) ? g_qh_lo : g_kh_lo;
        #pragma unroll
        for (int j = 0; j < 8; j++) {
            int col = 8 * j + 2 * t4;
            uint32_t hp0 = pack2(acc[j][0], acc[j][1]);
            float h0 = __uint_as_float(hp0 << 16), h1 = __uint_as_float(hp0 & 0xffff0000u);
            uint32_t lp0 = pack2(acc[j][0] - h0, acc[j][1] - h1);
            *(uint32_t*)&Oh[(size_t)row0 * HH + col] = hp0;
            *(uint32_t*)&Ol[(size_t)row0 * HH + col] = lp0;
            uint32_t hp1 = pack2(acc[j][2], acc[j][3]);
            float h2 = __uint_as_float(hp1 << 16), h3 = __uint_as_float(hp1 & 0xffff0000u);
            uint32_t lp1 = pack2(acc[j][2] - h2, acc[j][3] - h3);
            *(uint32_t*)&Oh[(size_t)(row0 + 8) * HH + col] = hp1;
            *(uint32_t*)&Ol[(size_t)(row0 + 8) * HH + col] = lp1;
        }
    } else {
        uint16_t* th = psm;
        uint16_t* tl = psm + 8192;
        #pragma unroll
        for (int j = 0; j < 8; j++) {
            int h = 8 * j + 2 * t4;
            #pragma unroll
            for (int e = 0; e < 4; e++) {
                int hc = h + (e & 1);
                int rr = rowA + ((e >= 2) ? 8 : 0);
                float val = acc[j][e];
                __nv_bfloat16 bh = __float2bfloat16(val);
                float res = val - __bfloat162float(bh);
                th[hc * 128 + rr] = __bfloat16_as_ushort(bh);
                tl[hc * 128 + rr] = __bfloat16_as_ushort(__float2bfloat16(res));
            }
        }
        __syncthreads();
        for (int i = tid; i < 1024; i += 256) {
            int h = i >> 4, c2 = i & 15;
            ((uint4*)(&g_vt_hi[(size_t)h * NT + m0]))[c2] = ((const uint4*)th)[h * 16 + c2];
            ((uint4*)(&g_vt_lo[(size_t)h * NT + m0]))[c2] = ((const uint4*)tl)[h * 16 + c2];
        }
    }
}

// ======================= flash attention: balanced co-residency pairing =======================
// 1-D grid of 256. bid -> (size s, instance) such that bid j and j+148 (same SM via
// LUT[bid%148]) have sizes summing to 28, and the 40 single-resident SMs (bids 108..147)
// carry the largest blocks (28..32). Sizes s = qb+1; 8 instances per size (4 batches x 2 halves).
__global__ __launch_bounds__(256, 2) void attn_tc()
{
    extern __shared__ uint16_t sm[];
    uint16_t* Qh = sm;
    uint16_t* Ql = sm + QSZ;
    const uint32_t smb = (uint32_t)__cvta_generic_to_shared(sm);
    const int tid = threadIdx.x, wid = tid >> 5, lane = tid & 31;
    const int g = lane >> 2, t4 = lane & 3;

    // balanced pairing map
    const int bid = blockIdx.x;
    int s, inst;
    if (bid < 104)      { s = 27 - (bid >> 3); inst = bid & 7; }
    else if (bid < 108) { s = 14;              inst = bid - 104; }
    else if (bid < 148) { int t = bid - 108; s = 32 - (t >> 3); inst = t & 7; }
    else if (bid < 252) { int t = bid - 148; s = 1 + (t >> 3);  inst = t & 7; }
    else                { s = 14;              inst = bid - 252 + 4; }
    const int qb = s - 1;
    const int half = inst & 1;
    const int b = inst >> 1;

    const int q0 = qb * 128, bT = b * TT;
    const int rowA = (wid << 4) + g;
    const int tstart = half ? (qb + 1) : 0;
    const int tend   = half ? (2 * qb + 2) : (qb + 1);
    const int n = tend - tstart;

    auto issue_tile = [&](int k0n, int bb) {
        const uint32_t base = smb + (uint32_t)(BUF0 + bb * BUFSZ) * 2;
        #pragma unroll
        for (int e = 0; e < 8; e++) {
            int idx = tid + 256 * e;
            int arr = idx >> 9, w = idx & 511;
            int r = w >> 3, c8 = (w & 7) << 3;
            uint32_t dst = base + (uint32_t)(arr * TSZ + r * APAD + c8) * 2;
            const void* src;
            if (arr == 0)      src = &g_kh_hi[(size_t)(bT + k0n + r) * HH + c8];
            else if (arr == 1) src = &g_kh_lo[(size_t)(bT + k0n + r) * HH + c8];
            else if (arr == 2) src = &g_vt_hi[(size_t)r * NT + bT + k0n + c8];
            else               src = &g_vt_lo[(size_t)r * NT + bT + k0n + c8];
            cpa16(dst, src);
        }
        CPA_COMMIT();
    };

    issue_tile(tstart * 64, 0);
    if (n > 1) issue_tile((tstart + 1) * 64, 1);
    for (int i = tid; i < 2048; i += 256) {
        int r = i >> 4, c4 = (i & 15) << 2;
        *(uint2*)&Qh[r * APAD + c4] = *(const uint2*)&g_qh_hi[(size_t)(bT + q0 + r) * HH + c4];
        *(uint2*)&Ql[r * APAD + c4] = *(const uint2*)&g_qh_lo[(size_t)(bT + q0 + r) * HH + c4];
    }

    float oacc[8][4] = {};
    float m0r = MFLOOR, m1r = MFLOOR, l0r = 0.0f, l1r = 0.0f;

    for (int i = 0; i < n; i++) {
        const int tt = tstart + i;
        const int k0 = tt * 64;
        const int cur = i & 1;

        if (i <= n - 2) { CPA_WAIT(1); } else { CPA_WAIT(0); }
        __syncthreads();

        uint16_t* Kh = sm + BUF0 + cur * BUFSZ;
        uint16_t* Kl = Kh + TSZ;
        uint16_t* Vh = Kh + 2 * TSZ;
        uint16_t* Vl = Kh + 3 * TSZ;

        // S = Q K^T : term-major passes
        float sacc[8][4] = {};
        #pragma unroll
        for (int c = 0; c < 4; c++) {
            const int kc = 16 * c + 2 * t4;
            uint32_t ah0 = *(uint32_t*)&Qh[rowA * APAD + kc],       ah1 = *(uint32_t*)&Qh[(rowA + 8) * APAD + kc];
            uint32_t ah2 = *(uint32_t*)&Qh[rowA * APAD + kc + 8],   ah3 = *(uint32_t*)&Qh[(rowA + 8) * APAD + kc + 8];
            uint32_t al0 = *(uint32_t*)&Ql[rowA * APAD + kc],       al1 = *(uint32_t*)&Ql[(rowA + 8) * APAD + kc];
            uint32_t al2 = *(uint32_t*)&Ql[rowA * APAD + kc + 8],   al3 = *(uint32_t*)&Ql[(rowA + 8) * APAD + kc + 8];
            #pragma unroll
            for (int j = 0; j < 8; j++) {
                int nn = 8 * j + g;
                mma16816(sacc[j], ah0, ah1, ah2, ah3,
                         *(uint32_t*)&Kh[nn * APAD + kc], *(uint32_t*)&Kh[nn * APAD + kc + 8]);
            }
            #pragma unroll
            for (int j = 0; j < 8; j++) {
                int nn = 8 * j + g;
                mma16816(sacc[j], al0, al1, al2, al3,
                         *(uint32_t*)&Kh[nn * APAD + kc], *(uint32_t*)&Kh[nn * APAD + kc + 8]);
            }
            #pragma unroll
            for (int j = 0; j < 8; j++) {
                int nn = 8 * j + g;
                mma16816(sacc[j], ah0, ah1, ah2, ah3,
                         *(uint32_t*)&Kl[nn * APAD + kc], *(uint32_t*)&Kl[nn * APAD + kc + 8]);
            }
        }

        // scale + causal mask
        const bool domask = (tt >= 2 * qb);
        #pragma unroll
        for (int j = 0; j < 8; j++) {
            int col = k0 + 8 * j + 2 * t4;
            #pragma unroll
            for (int e = 0; e < 4; e++) {
                float val = sacc[j][e] * 0.125f;
                if (domask) {
                    int rr = q0 + rowA + ((e >= 2) ? 8 : 0);
                    if (col + (e & 1) > rr) val = NEGINF;
                }
                sacc[j][e] = val;
            }
        }

        // online softmax (finite floor)
        float mx0 = NEGINF, mx1 = NEGINF;
        #pragma unroll
        for (int j = 0; j < 8; j++) {
            mx0 = fmaxf(mx0, fmaxf(sacc[j][0], sacc[j][1]));
            mx1 = fmaxf(mx1, fmaxf(sacc[j][2], sacc[j][3]));
        }
        mx0 = fmaxf(mx0, __shfl_xor_sync(0xffffffffu, mx0, 1));
        mx0 = fmaxf(mx0, __shfl_xor_sync(0xffffffffu, mx0, 2));
        mx1 = fmaxf(mx1, __shfl_xor_sync(0xffffffffu, mx1, 1));
        mx1 = fmaxf(mx1, __shfl_xor_sync(0xffffffffu, mx1, 2));
        const float mn0 = fmaxf(m0r, mx0), mn1 = fmaxf(m1r, mx1);
        const float corr0 = __expf(m0r - mn0), corr1 = __expf(m1r - mn1);
        float s0 = 0.0f, s1 = 0.0f;
        #pragma unroll
        for (int j = 0; j < 8; j++) {
            float p0 = __expf(sacc[j][0] - mn0), p1 = __expf(sacc[j][1] - mn0);
            float p2 = __expf(sacc[j][2] - mn1), p3 = __expf(sacc[j][3] - mn1);
            sacc[j][0] = p0; sacc[j][1] = p1; sacc[j][2] = p2; sacc[j][3] = p3;
            s0 += p0 + p1; s1 += p2 + p3;
        }
        s0 += __shfl_xor_sync(0xffffffffu, s0, 1);
        s0 += __shfl_xor_sync(0xffffffffu, s0, 2);
        s1 += __shfl_xor_sync(0xffffffffu, s1, 1);
        s1 += __shfl_xor_sync(0xffffffffu, s1, 2);
        l0r = l0r * corr0 + s0; l1r = l1r * corr1 + s1;
        m0r = mn0; m1r = mn1;

        #pragma unroll
        for (int j = 0; j < 8; j++) {
            oacc[j][0] *= corr0; oacc[j][1] *= corr0;
            oacc[j][2] *= corr1; oacc[j][3] *= corr1;
        }

        // O += P V : pack P per c-slice, term-major passes
        #pragma unroll
        for (int c = 0; c < 4; c++) {
            uint32_t ph0 = pack2(sacc[2*c][0],   sacc[2*c][1]);
            uint32_t ph1 = pack2(sacc[2*c][2],   sacc[2*c][3]);
            uint32_t ph2 = pack2(sacc[2*c+1][0], sacc[2*c+1][1]);
            uint32_t ph3 = pack2(sacc[2*c+1][2], sacc[2*c+1][3]);
            float r0 = sacc[2*c][0]   - __uint_as_float(ph0 << 16);
            float r1 = sacc[2*c][1]   - __uint_as_float(ph0 & 0xffff0000u);
            float r2 = sacc[2*c][2]   - __uint_as_float(ph1 << 16);
            float r3 = sacc[2*c][3]   - __uint_as_float(ph1 & 0xffff0000u);
            float r4 = sacc[2*c+1][0] - __uint_as_float(ph2 << 16);
            float r5 = sacc[2*c+1][1] - __uint_as_float(ph2 & 0xffff0000u);
            float r6 = sacc[2*c+1][2] - __uint_as_float(ph3 << 16);
            float r7 = sacc[2*c+1][3] - __uint_as_float(ph3 & 0xffff0000u);
            uint32_t pl0 = pack2(r0, r1), pl1 = pack2(r2, r3);
            uint32_t pl2 = pack2(r4, r5), pl3 = pack2(r6, r7);
            const int kc = 16 * c + 2 * t4;
            #pragma unroll
            for (int j2 = 0; j2 < 8; j2++) {
                int nn = 8 * j2 + g;
                mma16816(oacc[j2], ph0, ph1, ph2, ph3,
                         *(uint32_t*)&Vh[nn * APAD + kc], *(uint32_t*)&Vh[nn * APAD + kc + 8]);
            }
            #pragma unroll
            for (int j2 = 0; j2 < 8; j2++) {
                int nn = 8 * j2 + g;
                mma16816(oacc[j2], pl0, pl1, pl2, pl3,
                         *(uint32_t*)&Vh[nn * APAD + kc], *(uint32_t*)&Vh[nn * APAD + kc + 8]);
            }
            #pragma unroll
            for (int j2 = 0; j2 < 8; j2++) {
                int nn = 8 * j2 + g;
                mma16816(oacc[j2], ph0, ph1, ph2, ph3,
                         *(uint32_t*)&Vl[nn * APAD + kc], *(uint32_t*)&Vl[nn * APAD + kc + 8]);
            }
        }

        __syncthreads();
        if (i + 2 < n) issue_tile((tt + 2) * 64, cur);
    }

    float* po = g_po[half];
    #pragma unroll
    for (int j = 0; j < 8; j++) {
        int col = 8 * j + 2 * t4;
        *(float2*)&po[(size_t)(bT + q0 + rowA) * HH + col] = make_float2(oacc[j][0], oacc[j][1]);
        *(float2*)&po[(size_t)(bT + q0 + rowA + 8) * HH + col] = make_float2(oacc[j][2], oacc[j][3]);
    }
    if (t4 == 0) {
        g_pm[half][bT + q0 + rowA] = m0r;      g_pl[half][bT + q0 + rowA] = l0r;
        g_pm[half][bT + q0 + rowA + 8] = m1r;  g_pl[half][bT + q0 + rowA + 8] = l1r;
    }
}

// ======================= merge =======================
__global__ __launch_bounds__(256) void merge_k(float* __restrict__ out)
{
    const int idx = blockIdx.x * 256 + threadIdx.x;
    const int row = idx >> 4;
    const int c4 = (idx & 15) << 2;
    const float m0 = g_pm[0][row], m1 = g_pm[1][row];
    const float ms = fmaxf(m0, m1);
    const float w0 = __expf(m0 - ms), w1 = __expf(m1 - ms);
    const float inv = 1.0f / (g_pl[0][row] * w0 + g_pl[1][row] * w1);
    const float4 a = *(const float4*)&g_po[0][(size_t)row * HH + c4];
    const float4 bq = *(const float4*)&g_po[1][(size_t)row * HH + c4];
    *(float4*)&out[(size_t)row * HH + c4] = make_float4(
        (a.x * w0 + bq.x * w1) * inv, (a.y * w0 + bq.y * w1) * inv,
        (a.z * w0 + bq.z * w1) * inv, (a.w * w0 + bq.w * w1) * inv);
}

extern "C" void kernel_launch(void* const* d_in, const int* in_sizes, int n_in,
                              void* d_out, int out_size)
{
    const float* q  = (const float*)d_in[0];
    const float* k  = (const float*)d_in[1];
    const float* v  = (const float*)d_in[2];
    const float* Wq = (const float*)d_in[3];
    const float* Wk = (const float*)d_in[4];
    const float* Wv = (const float*)d_in[5];
    // d_in[6] (tril mask) implemented analytically

    wconv_k<<<768, 256>>>(Wq, Wk, Wv);

    const int proj_smem = 104448;
    cudaFuncSetAttribute(proj_tc, cudaFuncAttributeMaxDynamicSharedMemorySize, proj_smem);
    proj_tc<<<dim3(NT / 128, 3), 256, proj_smem>>>(q, k, v);

    cudaFuncSetAttribute(attn_tc, cudaFuncAttributeMaxDynamicSharedMemorySize, ATTN_SMEM_BYTES);
    attn_tc<<<256, 256, ATTN_SMEM_BYTES>>>();

    merge_k<<<(NT * HH / 4) / 256, 256>>>((float*)d_out);
}

// round 15
// speedup vs baseline: 1.2233x; 1.0705x over previous
#include <cuda_runtime.h>
#include <cuda_bf16.h>
#include <cstdint>

#define BB 4
#define TT 4096
#define DD 1024
#define HH 64
#define NT (BB*TT)
#define NQB (TT/128)
#define NSLOT 8
#define NCHBLK 576   // 4 * sum_qb ceil((qb+1)/4)

#define NEGINF __int_as_float(0xff800000)
#define MFLOOR (-1e30f)

// attn smem geometry (uint16 units): row pad 72 (144 B, 16B-aligned rows for cp.async)
#define APAD 72
#define QSZ  (128*APAD)
#define TSZ  (64*APAD)
#define BUF0 (2*QSZ)
#define BUFSZ (4*TSZ)
#define ATTN_SMEM_BYTES ((BUF0 + 2*BUFSZ) * 2)   // 110592

__device__ __nv_bfloat16 g_qh_hi[NT*HH], g_qh_lo[NT*HH];
__device__ __nv_bfloat16 g_kh_hi[NT*HH], g_kh_lo[NT*HH];
__device__ __nv_bfloat16 g_vt_hi[HH*NT], g_vt_lo[HH*NT];
__device__ __nv_bfloat16 g_wt_hi[3][HH*DD], g_wt_lo[3][HH*DD];
// chunked split-KV partials: up to 8 slots per row
__device__ float g_poc[NSLOT][NT*HH];
__device__ float g_pmc[NSLOT][NT];
__device__ float g_plc[NSLOT][NT];

__device__ __forceinline__ uint32_t pack2(float lo, float hi) {
    uint32_t r;
    asm("cvt.rn.bf16x2.f32 %0, %1, %2;" : "=r"(r) : "f"(hi), "f"(lo));
    return r;
}
__device__ __forceinline__ void mma16816(float* d, uint32_t a0, uint32_t a1, uint32_t a2, uint32_t a3,
                                         uint32_t b0, uint32_t b1) {
    asm volatile("mma.sync.aligned.m16n8k16.row.col.f32.bf16.bf16.f32 "
        "{%0,%1,%2,%3}, {%4,%5,%6,%7}, {%8,%9}, {%0,%1,%2,%3};"
        : "+f"(d[0]), "+f"(d[1]), "+f"(d[2]), "+f"(d[3])
        : "r"(a0), "r"(a1), "r"(a2), "r"(a3), "r"(b0), "r"(b1));
}
__device__ __forceinline__ void cpa16(uint32_t dst, const void* src) {
    asm volatile("cp.async.cg.shared.global [%0], [%1], 16;" :: "r"(dst), "l"(src));
}
#define CPA_COMMIT() asm volatile("cp.async.commit_group;" ::: "memory")
#define CPA_WAIT(n)  asm volatile("cp.async.wait_group %0;" :: "n"(n) : "memory")

// ======================= W pre-conversion =======================
__global__ __launch_bounds__(256) void wconv_k(
    const float* __restrict__ Wq, const float* __restrict__ Wk, const float* __restrict__ Wv)
{
    const int gid = blockIdx.x * 256 + threadIdx.x;
    const int y = gid >> 16;
    const int rem = gid & 65535;
    const int n = rem >> 10, k = rem & 1023;
    const float* W = (y == 0) ? Wq : (y == 1) ? Wk : Wv;
    float w = W[(size_t)k * HH + n];
    __nv_bfloat16 bh = __float2bfloat16(w);
    g_wt_hi[y][(size_t)n * DD + k] = bh;
    g_wt_lo[y][(size_t)n * DD + k] = __float2bfloat16(w - __bfloat162float(bh));
}

// ======================= projection (unchanged from R14) =======================
__global__ __launch_bounds__(256) void proj_tc(
    const float* __restrict__ q, const float* __restrict__ k, const float* __restrict__ v)
{
    extern __shared__ uint16_t psm[];
    uint16_t* Xhb[2] = {psm,         psm + 26112};
    uint16_t* Xlb[2] = {psm + 8704,  psm + 34816};
    uint16_t* Whb[2] = {psm + 17408, psm + 43520};
    uint16_t* Wlb[2] = {psm + 21760, psm + 47872};

    const int tid = threadIdx.x, wid = tid >> 5, lane = tid & 31;
    const int g = lane >> 2, t4 = lane & 3;
    const int y = blockIdx.y;
    const float* X = (y == 0) ? q : (y == 1) ? k : v;
    const __nv_bfloat16* gwh = g_wt_hi[y];
    const __nv_bfloat16* gwl = g_wt_lo[y];
    const int m0 = blockIdx.x * 128;
    const int rowA = (wid << 4) + g;

    float4 xv[8];
    uint4 wh4[2], wl4[2];

    auto load_regs = [&](int c0) {
        #pragma unroll
        for (int e = 0; e < 8; e++) {
            int idx = tid + 256 * e, r = idx >> 4, c4 = (idx & 15) << 2;
            xv[e] = *(const float4*)&X[(size_t)(m0 + r) * DD + c0 + c4];
        }
        #pragma unroll
        for (int e = 0; e < 2; e++) {
            int idx = tid + 256 * e, n = idx >> 3, k8 = (idx & 7) << 3;
            wh4[e] = *(const uint4*)&gwh[(size_t)n * DD + c0 + k8];
            wl4[e] = *(const uint4*)&gwl[(size_t)n * DD + c0 + k8];
        }
    };
    auto store_chunk = [&](int bb) {
        #pragma unroll
        for (int e = 0; e < 8; e++) {
            int idx = tid + 256 * e, r = idx >> 4, c4 = (idx & 15) << 2;
            float4 x = xv[e];
            uint32_t h01 = pack2(x.x, x.y), h23 = pack2(x.z, x.w);
            float hx = __uint_as_float(h01 << 16), hy = __uint_as_float(h01 & 0xffff0000u);
            float hz = __uint_as_float(h23 << 16), hw = __uint_as_float(h23 & 0xffff0000u);
            uint32_t l01 = pack2(x.x - hx, x.y - hy), l23 = pack2(x.z - hz, x.w - hw);
            *(uint32_t*)&Xhb[bb][r * 68 + c4]     = h01;
            *(uint32_t*)&Xhb[bb][r * 68 + c4 + 2] = h23;
            *(uint32_t*)&Xlb[bb][r * 68 + c4]     = l01;
            *(uint32_t*)&Xlb[bb][r * 68 + c4 + 2] = l23;
        }
        #pragma unroll
        for (int e = 0; e < 2; e++) {
            int idx = tid + 256 * e, n = idx >> 3, k8 = (idx & 7) << 3;
            const uint32_t* sh = (const uint32_t*)&wh4[e];
            const uint32_t* sl = (const uint32_t*)&wl4[e];
            #pragma unroll
            for (int u = 0; u < 4; u++) {
                *(uint32_t*)&Whb[bb][n * 68 + k8 + 2 * u] = sh[u];
                *(uint32_t*)&Wlb[bb][n * 68 + k8 + 2 * u] = sl[u];
            }
        }
    };

    float acc[8][4] = {};

    load_regs(0);
    store_chunk(0);
    __syncthreads();

    for (int c = 0; c < 16; c++) {
        const int cur = c & 1, nxt = cur ^ 1;
        const bool more = (c + 1 < 16);
        if (more) load_regs((c + 1) * 64);

        uint16_t* Xh = Xhb[cur]; uint16_t* Xl = Xlb[cur];
        uint16_t* Wh = Whb[cur]; uint16_t* Wl = Wlb[cur];
        #pragma unroll
        for (int cs = 0; cs < 4; cs++) {
            const int kc = cs * 16 + 2 * t4;
            uint32_t ah0 = *(uint32_t*)&Xh[rowA * 68 + kc],       ah1 = *(uint32_t*)&Xh[(rowA + 8) * 68 + kc];
            uint32_t ah2 = *(uint32_t*)&Xh[rowA * 68 + kc + 8],   ah3 = *(uint32_t*)&Xh[(rowA + 8) * 68 + kc + 8];
            uint32_t al0 = *(uint32_t*)&Xl[rowA * 68 + kc],       al1 = *(uint32_t*)&Xl[(rowA + 8) * 68 + kc];
            uint32_t al2 = *(uint32_t*)&Xl[rowA * 68 + kc + 8],   al3 = *(uint32_t*)&Xl[(rowA + 8) * 68 + kc + 8];
            #pragma unroll
            for (int j = 0; j < 8; j++) {
                int n = 8 * j + g;
                mma16816(acc[j], ah0, ah1, ah2, ah3,
                         *(uint32_t*)&Wh[n * 68 + kc], *(uint32_t*)&Wh[n * 68 + kc + 8]);
            }
            #pragma unroll
            for (int j = 0; j < 8; j++) {
                int n = 8 * j + g;
                mma16816(acc[j], al0, al1, al2, al3,
                         *(uint32_t*)&Wh[n * 68 + kc], *(uint32_t*)&Wh[n * 68 + kc + 8]);
            }
            #pragma unroll
            for (int j = 0; j < 8; j++) {
                int n = 8 * j + g;
                mma16816(acc[j], ah0, ah1, ah2, ah3,
                         *(uint32_t*)&Wl[n * 68 + kc], *(uint32_t*)&Wl[n * 68 + kc + 8]);
            }
        }
        if (more) store_chunk(nxt);
        __syncthreads();
    }

    const int row0 = m0 + rowA;
    if (y < 2) {
        __nv_bfloat16* Oh = (y == 0) ? g_qh_hi : g_kh_hi;
        __nv_bfloat16* Ol = (y == 0) ? g_qh_lo : g_kh_lo;
        #pragma unroll
        for (int j = 0; j < 8; j++) {
            int col = 8 * j + 2 * t4;
            uint32_t hp0 = pack2(acc[j][0], acc[j][1]);
            float h0 = __uint_as_float(hp0 << 16), h1 = __uint_as_float(hp0 & 0xffff0000u);
            uint32_t lp0 = pack2(acc[j][0] - h0, acc[j][1] - h1);
            *(uint32_t*)&Oh[(size_t)row0 * HH + col] = hp0;
            *(uint32_t*)&Ol[(size_t)row0 * HH + col] = lp0;
            uint32_t hp1 = pack2(acc[j][2], acc[j][3]);
            float h2 = __uint_as_float(hp1 << 16), h3 = __uint_as_float(hp1 & 0xffff0000u);
            uint32_t lp1 = pack2(acc[j][2] - h2, acc[j][3] - h3);
            *(uint32_t*)&Oh[(size_t)(row0 + 8) * HH + col] = hp1;
            *(uint32_t*)&Ol[(size_t)(row0 + 8) * HH + col] = lp1;
        }
    } else {
        uint16_t* th = psm;
        uint16_t* tl = psm + 8192;
        #pragma unroll
        for (int j = 0; j < 8; j++) {
            int h = 8 * j + 2 * t4;
            #pragma unroll
            for (int e = 0; e < 4; e++) {
                int hc = h + (e & 1);
                int rr = rowA + ((e >= 2) ? 8 : 0);
                float val = acc[j][e];
                __nv_bfloat16 bh = __float2bfloat16(val);
                float res = val - __bfloat162float(bh);
                th[hc * 128 + rr] = __bfloat16_as_ushort(bh);
                tl[hc * 128 + rr] = __bfloat16_as_ushort(__float2bfloat16(res));
            }
        }
        __syncthreads();
        for (int i = tid; i < 1024; i += 256) {
            int h = i >> 4, c2 = i & 15;
            ((uint4*)(&g_vt_hi[(size_t)h * NT + m0]))[c2] = ((const uint4*)th)[h * 16 + c2];
            ((uint4*)(&g_vt_lo[(size_t)h * NT + m0]))[c2] = ((const uint4*)tl)[h * 16 + c2];
        }
    }
}

// ======================= flash attention: chunked split-KV (<=8 tiles/block) =======================
// 576 blocks, longest-qb first. bid -> (qb desc, chunk ci, batch b). Near-uniform block sizes
// make makespan placement-insensitive; HW work-stealing handles the 2nd wave.
__global__ __launch_bounds__(256, 2) void attn_tc()
{
    extern __shared__ uint16_t sm[];
    uint16_t* Qh = sm;
    uint16_t* Ql = sm + QSZ;
    const uint32_t smb = (uint32_t)__cvta_generic_to_shared(sm);
    const int tid = threadIdx.x, wid = tid >> 5, lane = tid & 31;
    const int g = lane >> 2, t4 = lane & 3;

    // bid -> (qb, ci, b): qb descending, nch(qb) = ceil((qb+1)/4) chunks, 4 batches each
    const int b = blockIdx.x & 3;
    int rem = blockIdx.x >> 2;          // 0..143
    int qb = 31, ci = 0;
    #pragma unroll 1
    for (int qq = 31; qq >= 0; qq--) {
        int nch = (qq + 4) >> 2;
        if (rem < nch) { qb = qq; ci = rem; break; }
        rem -= nch;
    }

    const int q0 = qb * 128, bT = b * TT;
    const int rowA = (wid << 4) + g;
    const int ntiles = 2 * qb + 2;
    const int tstart = ci * 8;
    const int tend = (tstart + 8 < ntiles) ? (tstart + 8) : ntiles;
    const int n = tend - tstart;

    auto issue_tile = [&](int k0n, int bb) {
        const uint32_t base = smb + (uint32_t)(BUF0 + bb * BUFSZ) * 2;
        #pragma unroll
        for (int e = 0; e < 8; e++) {
            int idx = tid + 256 * e;
            int arr = idx >> 9, w = idx & 511;
            int r = w >> 3, c8 = (w & 7) << 3;
            uint32_t dst = base + (uint32_t)(arr * TSZ + r * APAD + c8) * 2;
            const void* src;
            if (arr == 0)      src = &g_kh_hi[(size_t)(bT + k0n + r) * HH + c8];
            else if (arr == 1) src = &g_kh_lo[(size_t)(bT + k0n + r) * HH + c8];
            else if (arr == 2) src = &g_vt_hi[(size_t)r * NT + bT + k0n + c8];
            else               src = &g_vt_lo[(size_t)r * NT + bT + k0n + c8];
            cpa16(dst, src);
        }
        CPA_COMMIT();
    };

    issue_tile(tstart * 64, 0);
    if (n > 1) issue_tile((tstart + 1) * 64, 1);
    for (int i = tid; i < 2048; i += 256) {
        int r = i >> 4, c4 = (i & 15) << 2;
        *(uint2*)&Qh[r * APAD + c4] = *(const uint2*)&g_qh_hi[(size_t)(bT + q0 + r) * HH + c4];
        *(uint2*)&Ql[r * APAD + c4] = *(const uint2*)&g_qh_lo[(size_t)(bT + q0 + r) * HH + c4];
    }

    float oacc[8][4] = {};
    float m0r = MFLOOR, m1r = MFLOOR, l0r = 0.0f, l1r = 0.0f;

    for (int i = 0; i < n; i++) {
        const int tt = tstart + i;
        const int k0 = tt * 64;
        const int cur = i & 1;

        if (i <= n - 2) { CPA_WAIT(1); } else { CPA_WAIT(0); }
        __syncthreads();

        uint16_t* Kh = sm + BUF0 + cur * BUFSZ;
        uint16_t* Kl = Kh + TSZ;
        uint16_t* Vh = Kh + 2 * TSZ;
        uint16_t* Vl = Kh + 3 * TSZ;

        // S = Q K^T : term-major passes
        float sacc[8][4] = {};
        #pragma unroll
        for (int c = 0; c < 4; c++) {
            const int kc = 16 * c + 2 * t4;
            uint32_t ah0 = *(uint32_t*)&Qh[rowA * APAD + kc],       ah1 = *(uint32_t*)&Qh[(rowA + 8) * APAD + kc];
            uint32_t ah2 = *(uint32_t*)&Qh[rowA * APAD + kc + 8],   ah3 = *(uint32_t*)&Qh[(rowA + 8) * APAD + kc + 8];
            uint32_t al0 = *(uint32_t*)&Ql[rowA * APAD + kc],       al1 = *(uint32_t*)&Ql[(rowA + 8) * APAD + kc];
            uint32_t al2 = *(uint32_t*)&Ql[rowA * APAD + kc + 8],   al3 = *(uint32_t*)&Ql[(rowA + 8) * APAD + kc + 8];
            #pragma unroll
            for (int j = 0; j < 8; j++) {
                int nn = 8 * j + g;
                mma16816(sacc[j], ah0, ah1, ah2, ah3,
                         *(uint32_t*)&Kh[nn * APAD + kc], *(uint32_t*)&Kh[nn * APAD + kc + 8]);
            }
            #pragma unroll
            for (int j = 0; j < 8; j++) {
                int nn = 8 * j + g;
                mma16816(sacc[j], al0, al1, al2, al3,
                         *(uint32_t*)&Kh[nn * APAD + kc], *(uint32_t*)&Kh[nn * APAD + kc + 8]);
            }
            #pragma unroll
            for (int j = 0; j < 8; j++) {
                int nn = 8 * j + g;
                mma16816(sacc[j], ah0, ah1, ah2, ah3,
                         *(uint32_t*)&Kl[nn * APAD + kc], *(uint32_t*)&Kl[nn * APAD + kc + 8]);
            }
        }

        // scale + causal mask
        const bool domask = (tt >= 2 * qb);
        #pragma unroll
        for (int j = 0; j < 8; j++) {
            int col = k0 + 8 * j + 2 * t4;
            #pragma unroll
            for (int e = 0; e < 4; e++) {
                float val = sacc[j][e] * 0.125f;
                if (domask) {
                    int rr = q0 + rowA + ((e >= 2) ? 8 : 0);
                    if (col + (e & 1) > rr) val = NEGINF;
                }
                sacc[j][e] = val;
            }
        }

        // online softmax (finite floor)
        float mx0 = NEGINF, mx1 = NEGINF;
        #pragma unroll
        for (int j = 0; j < 8; j++) {
            mx0 = fmaxf(mx0, fmaxf(sacc[j][0], sacc[j][1]));
            mx1 = fmaxf(mx1, fmaxf(sacc[j][2], sacc[j][3]));
        }
        mx0 = fmaxf(mx0, __shfl_xor_sync(0xffffffffu, mx0, 1));
        mx0 = fmaxf(mx0, __shfl_xor_sync(0xffffffffu, mx0, 2));
        mx1 = fmaxf(mx1, __shfl_xor_sync(0xffffffffu, mx1, 1));
        mx1 = fmaxf(mx1, __shfl_xor_sync(0xffffffffu, mx1, 2));
        const float mn0 = fmaxf(m0r, mx0), mn1 = fmaxf(m1r, mx1);
        const float corr0 = __expf(m0r - mn0), corr1 = __expf(m1r - mn1);
        float s0 = 0.0f, s1 = 0.0f;
        #pragma unroll
        for (int j = 0; j < 8; j++) {
            float p0 = __expf(sacc[j][0] - mn0), p1 = __expf(sacc[j][1] - mn0);
            float p2 = __expf(sacc[j][2] - mn1), p3 = __expf(sacc[j][3] - mn1);
            sacc[j][0] = p0; sacc[j][1] = p1; sacc[j][2] = p2; sacc[j][3] = p3;
            s0 += p0 + p1; s1 += p2 + p3;
        }
        s0 += __shfl_xor_sync(0xffffffffu, s0, 1);
        s0 += __shfl_xor_sync(0xffffffffu, s0, 2);
        s1 += __shfl_xor_sync(0xffffffffu, s1, 1);
        s1 += __shfl_xor_sync(0xffffffffu, s1, 2);
        l0r = l0r * corr0 + s0; l1r = l1r * corr1 + s1;
        m0r = mn0; m1r = mn1;

        #pragma unroll
        for (int j = 0; j < 8; j++) {
            oacc[j][0] *= corr0; oacc[j][1] *= corr0;
            oacc[j][2] *= corr1; oacc[j][3] *= corr1;
        }

        // O += P V : pack P per c-slice, term-major passes
        #pragma unroll
        for (int c = 0; c < 4; c++) {
            uint32_t ph0 = pack2(sacc[2*c][0],   sacc[2*c][1]);
            uint32_t ph1 = pack2(sacc[2*c][2],   sacc[2*c][3]);
            uint32_t ph2 = pack2(sacc[2*c+1][0], sacc[2*c+1][1]);
            uint32_t ph3 = pack2(sacc[2*c+1][2], sacc[2*c+1][3]);
            float r0 = sacc[2*c][0]   - __uint_as_float(ph0 << 16);
            float r1 = sacc[2*c][1]   - __uint_as_float(ph0 & 0xffff0000u);
            float r2 = sacc[2*c][2]   - __uint_as_float(ph1 << 16);
            float r3 = sacc[2*c][3]   - __uint_as_float(ph1 & 0xffff0000u);
            float r4 = sacc[2*c+1][0] - __uint_as_float(ph2 << 16);
            float r5 = sacc[2*c+1][1] - __uint_as_float(ph2 & 0xffff0000u);
            float r6 = sacc[2*c+1][2] - __uint_as_float(ph3 << 16);
            float r7 = sacc[2*c+1][3] - __uint_as_float(ph3 & 0xffff0000u);
            uint32_t pl0 = pack2(r0, r1), pl1 = pack2(r2, r3);
            uint32_t pl2 = pack2(r4, r5), pl3 = pack2(r6, r7);
            const int kc = 16 * c + 2 * t4;
            #pragma unroll
            for (int j2 = 0; j2 < 8; j2++) {
                int nn = 8 * j2 + g;
                mma16816(oacc[j2], ph0, ph1, ph2, ph3,
                         *(uint32_t*)&Vh[nn * APAD + kc], *(uint32_t*)&Vh[nn * APAD + kc + 8]);
            }
            #pragma unroll
            for (int j2 = 0; j2 < 8; j2++) {
                int nn = 8 * j2 + g;
                mma16816(oacc[j2], pl0, pl1, pl2, pl3,
                         *(uint32_t*)&Vh[nn * APAD + kc], *(uint32_t*)&Vh[nn * APAD + kc + 8]);
            }
            #pragma unroll
            for (int j2 = 0; j2 < 8; j2++) {
                int nn = 8 * j2 + g;
                mma16816(oacc[j2], ph0, ph1, ph2, ph3,
                         *(uint32_t*)&Vl[nn * APAD + kc], *(uint32_t*)&Vl[nn * APAD + kc + 8]);
            }
        }

        __syncthreads();
        if (i + 2 < n) issue_tile((tt + 2) * 64, cur);
    }

    // store partials into slot ci
    float* po = g_poc[ci];
    #pragma unroll
    for (int j = 0; j < 8; j++) {
        int col = 8 * j + 2 * t4;
        *(float2*)&po[(size_t)(bT + q0 + rowA) * HH + col] = make_float2(oacc[j][0], oacc[j][1]);
        *(float2*)&po[(size_t)(bT + q0 + rowA + 8) * HH + col] = make_float2(oacc[j][2], oacc[j][3]);
    }
    if (t4 == 0) {
        g_pmc[ci][bT + q0 + rowA] = m0r;      g_plc[ci][bT + q0 + rowA] = l0r;
        g_pmc[ci][bT + q0 + rowA + 8] = m1r;  g_plc[ci][bT + q0 + rowA + 8] = l1r;
    }
}

// ======================= merge up to 8 chunk partials per row =======================
__global__ __launch_bounds__(256) void merge_k(float* __restrict__ out)
{
    const int idx = blockIdx.x * 256 + threadIdx.x;
    const int row = idx >> 4;
    const int c4 = (idx & 15) << 2;
    const int qb = (row & (TT - 1)) >> 7;
    const int nch = (qb + 4) >> 2;

    float ms = MFLOOR;
    #pragma unroll 1
    for (int s = 0; s < nch; s++) ms = fmaxf(ms, g_pmc[s][row]);
    float den = 0.0f;
    float acc0 = 0.0f, acc1 = 0.0f, acc2 = 0.0f, acc3 = 0.0f;
    #pragma unroll 1
    for (int s = 0; s < nch; s++) {
        const float w = __expf(g_pmc[s][row] - ms);
        den += g_plc[s][row] * w;
        const float4 a = *(const float4*)&g_poc[s][(size_t)row * HH + c4];
        acc0 += a.x * w; acc1 += a.y * w; acc2 += a.z * w; acc3 += a.w * w;
    }
    const float inv = 1.0f / den;
    *(float4*)&out[(size_t)row * HH + c4] = make_float4(acc0 * inv, acc1 * inv, acc2 * inv, acc3 * inv);
}

extern "C" void kernel_launch(void* const* d_in, const int* in_sizes, int n_in,
                              void* d_out, int out_size)
{
    const float* q  = (const float*)d_in[0];
    const float* k  = (const float*)d_in[1];
    const float* v  = (const float*)d_in[2];
    const float* Wq = (const float*)d_in[3];
    const float* Wk = (const float*)d_in[4];
    const float* Wv = (const float*)d_in[5];
    // d_in[6] (tril mask) implemented analytically

    wconv_k<<<768, 256>>>(Wq, Wk, Wv);

    const int proj_smem = 104448;
    cudaFuncSetAttribute(proj_tc, cudaFuncAttributeMaxDynamicSharedMemorySize, proj_smem);
    proj_tc<<<dim3(NT / 128, 3), 256, proj_smem>>>(q, k, v);

    cudaFuncSetAttribute(attn_tc, cudaFuncAttributeMaxDynamicSharedMemorySize, ATTN_SMEM_BYTES);
    attn_tc<<<NCHBLK, 256, ATTN_SMEM_BYTES>>>();

    merge_k<<<(NT * HH / 4) / 256, 256>>>((float*)d_out);
}